// round 7
// baseline (speedup 1.0000x reference)
#include <cuda_runtime.h>
#include <cuda_bf16.h>
#include <math.h>
#include <cstdint>

// ---------------- problem constants ----------------
#define LQ   2048
#define HIDN 1024
#define NH   16
#define HD   64
#define FFD  4096
#define PW   128
#define NP   257

// ---------------- scratch ----------------
// f32 buffers
__device__ float g_q  [LQ * HIDN];
__device__ float g_k  [LQ * HIDN];
__device__ float g_v  [LQ * HIDN];
__device__ float g_h  [LQ * HIDN];
__device__ float g_c2p[NH * LQ * NP];
__device__ float g_p2c[NH * LQ * NP];
// bf16 split pairs, packed 2 elems per uint32 (even elem in low 16 bits)
__device__ uint32_t g_x1h [LQ * HIDN / 2];
__device__ uint32_t g_x1l [LQ * HIDN / 2];
__device__ uint32_t g_x2h [LQ * HIDN / 2];
__device__ uint32_t g_x2l [LQ * HIDN / 2];
__device__ uint32_t g_ctxh[LQ * HIDN / 2];
__device__ uint32_t g_ctxl[LQ * HIDN / 2];
__device__ uint32_t g_ffh [LQ * FFD  / 2];
__device__ uint32_t g_ffl [LQ * FFD  / 2];
// transposed split weights: [N][K/2] words
__device__ uint32_t g_wqh[HIDN * HIDN / 2];
__device__ uint32_t g_wql[HIDN * HIDN / 2];
__device__ uint32_t g_wkh[HIDN * HIDN / 2];
__device__ uint32_t g_wkl[HIDN * HIDN / 2];
__device__ uint32_t g_wvh[HIDN * HIDN / 2];
__device__ uint32_t g_wvl[HIDN * HIDN / 2];
__device__ uint32_t g_woh[HIDN * HIDN / 2];
__device__ uint32_t g_wol[HIDN * HIDN / 2];
__device__ uint32_t g_w1h[FFD * HIDN / 2];
__device__ uint32_t g_w1l[FFD * HIDN / 2];
__device__ uint32_t g_w2h[HIDN * FFD / 2];
__device__ uint32_t g_w2l[HIDN * FFD / 2];

// ---------------- helpers ----------------
__device__ __forceinline__ uint32_t smem_u32(const void* p) {
    uint32_t a;
    asm("{ .reg .u64 t; cvta.to.shared.u64 t, %1; cvt.u32.u64 %0, t; }"
        : "=r"(a) : "l"(p));
    return a;
}

#define CP_ASYNC16(dst, src) \
    asm volatile("cp.async.cg.shared.global [%0], [%1], 16;" \
                 :: "r"(dst), "l"(src) : "memory")
#define CP_ASYNC_COMMIT() asm volatile("cp.async.commit_group;" ::: "memory")
#define CP_ASYNC_WAIT0()  asm volatile("cp.async.wait_group 0;" ::: "memory")

// split x0,x1 into packed bf16 hi pair and lo pair (x0 -> low 16 bits)
__device__ __forceinline__ void split2(float x0, float x1,
                                       uint32_t& hi, uint32_t& lo)
{
    asm("cvt.rn.bf16x2.f32 %0, %1, %2;" : "=r"(hi) : "f"(x1), "f"(x0));
    float f0 = __uint_as_float(hi << 16);
    float f1 = __uint_as_float(hi & 0xffff0000u);
    float l0 = x0 - f0, l1 = x1 - f1;
    asm("cvt.rn.bf16x2.f32 %0, %1, %2;" : "=r"(lo) : "f"(l1), "f"(l0));
}

// bf16 m16n8k16 mma (baseline PTX sm_80+)
__device__ __forceinline__ void mma_bf16(float* d, const uint32_t* a,
                                         const uint32_t* b)
{
    asm volatile(
        "mma.sync.aligned.m16n8k16.row.col.f32.bf16.bf16.f32 "
        "{%0,%1,%2,%3}, {%4,%5,%6,%7}, {%8,%9}, {%0,%1,%2,%3};"
        : "+f"(d[0]), "+f"(d[1]), "+f"(d[2]), "+f"(d[3])
        : "r"(a[0]), "r"(a[1]), "r"(a[2]), "r"(a[3]),
          "r"(b[0]), "r"(b[1]));
}

__device__ __forceinline__ float gelu_exact(float x) {
    return 0.5f * x * (1.0f + erff(x * 0.70710678118654752440f));
}

// ---------------- transpose + split: src[R,C] f32 -> dh/dl [C][R/2] words ----
__global__ void __launch_bounds__(256) transpose_split_kernel(
    const float* __restrict__ src, uint32_t* __restrict__ dh,
    uint32_t* __restrict__ dl, int R, int C)
{
    __shared__ float tl[32][33];
    int c0 = blockIdx.x * 32, r0 = blockIdx.y * 32;
    int x = threadIdx.x & 31, y = threadIdx.x >> 5;
    #pragma unroll
    for (int i = 0; i < 32; i += 8)
        tl[y + i][x] = src[(size_t)(r0 + y + i) * C + c0 + x];
    __syncthreads();
    int xx = threadIdx.x & 15;        // word index within tile
    int yy = threadIdx.x >> 4;        // 0..15
    int Rw = R >> 1;
    #pragma unroll
    for (int i = 0; i < 2; i++) {
        int n = c0 + yy + i * 16;
        uint32_t hi, lo;
        split2(tl[2 * xx][yy + i * 16], tl[2 * xx + 1][yy + i * 16], hi, lo);
        dh[(size_t)n * Rw + (r0 >> 1) + xx] = hi;
        dl[(size_t)n * Rw + (r0 >> 1) + xx] = lo;
    }
}

// ---------------- bf16x3 GEMM ----------------
// C[M,N] = A[M,K] @ Bt[N,K]^T via (ah+al)(bh+bl) minus al*bl.
// Tile 128x128, K-chunk 32 (16 words), 8 warps (4x2), cp.async dbl-buffer.
#define WPITCH 20
#define ARRW (128 * WPITCH)          // 2560 words per array
#define BUFW (4 * ARRW)              // Ahi Alo Bhi Blo
#define TG_SMEM 81920                // max(2*BUFW*4, 128*132*4)

template <bool GELU, bool RES, bool PAIR_OUT>
__global__ void __launch_bounds__(256) tgemm_kernel(
    int M, int N, int K,
    const uint32_t* __restrict__ Ah, const uint32_t* __restrict__ Al,
    const uint32_t* __restrict__ Bh, const uint32_t* __restrict__ Bl,
    float* __restrict__ C, uint32_t* __restrict__ Ch,
    uint32_t* __restrict__ Cl,
    const float* __restrict__ bias, const float* __restrict__ res)
{
    extern __shared__ uint32_t smw[];
    uint32_t sb = smem_u32(smw);
    const int t    = threadIdx.x;
    const int wid  = t >> 5;
    const int lane = t & 31;
    const int g    = lane >> 2;
    const int c    = lane & 3;
    const int wm   = wid & 3;
    const int wn   = wid >> 2;
    const int bm   = blockIdx.y * 128;
    const int bn   = blockIdx.x * 128;
    const int Kw   = K >> 1;
    const int nk   = K >> 5;

    float acc[2][8][4];
    #pragma unroll
    for (int mt = 0; mt < 2; mt++)
        #pragma unroll
        for (int nt = 0; nt < 8; nt++)
            #pragma unroll
            for (int r = 0; r < 4; r++) acc[mt][nt][r] = 0.0f;

    auto load_chunk = [&](int ck, int buf) {
        uint32_t db = sb + buf * (BUFW * 4u);
        #pragma unroll
        for (int half = 0; half < 2; half++) {
            int id = t + 256 * half;       // 0..511
            int r  = id >> 2;              // 0..127
            int f  = (id & 3) * 4;         // word offset in chunk row
            uint32_t doff = (uint32_t)(r * WPITCH + f) * 4u;
            size_t ao = (size_t)(bm + r) * Kw + ck * 16 + f;
            size_t bo = (size_t)(bn + r) * Kw + ck * 16 + f;
            CP_ASYNC16(db + doff,                Ah + ao);
            CP_ASYNC16(db + ARRW * 4u + doff,    Al + ao);
            CP_ASYNC16(db + 2u * ARRW * 4u + doff, Bh + bo);
            CP_ASYNC16(db + 3u * ARRW * 4u + doff, Bl + bo);
        }
    };

    load_chunk(0, 0);
    CP_ASYNC_COMMIT();

    for (int i = 0; i < nk; i++) {
        CP_ASYNC_WAIT0();
        __syncthreads();
        if (i + 1 < nk) { load_chunk(i + 1, (i + 1) & 1); CP_ASYNC_COMMIT(); }

        const uint32_t* Ash = smw + (i & 1) * BUFW;
        const uint32_t* Asl = Ash + ARRW;
        const uint32_t* Bsh = Ash + 2 * ARRW;
        const uint32_t* Bsl = Ash + 3 * ARRW;

        #pragma unroll
        for (int s = 0; s < 2; s++) {
            uint32_t ah[2][4], al[2][4], bh[8][2], bl[8][2];
            #pragma unroll
            for (int mt = 0; mt < 2; mt++) {
                int base = (wm * 32 + mt * 16 + g) * WPITCH + s * 8 + c;
                ah[mt][0] = Ash[base];
                ah[mt][1] = Ash[base + 8 * WPITCH];
                ah[mt][2] = Ash[base + 4];
                ah[mt][3] = Ash[base + 8 * WPITCH + 4];
                al[mt][0] = Asl[base];
                al[mt][1] = Asl[base + 8 * WPITCH];
                al[mt][2] = Asl[base + 4];
                al[mt][3] = Asl[base + 8 * WPITCH + 4];
            }
            #pragma unroll
            for (int nt = 0; nt < 8; nt++) {
                int rb = (wn * 64 + nt * 8 + g) * WPITCH + s * 8 + c;
                bh[nt][0] = Bsh[rb];
                bh[nt][1] = Bsh[rb + 4];
                bl[nt][0] = Bsl[rb];
                bl[nt][1] = Bsl[rb + 4];
            }
            #pragma unroll
            for (int mt = 0; mt < 2; mt++)
                #pragma unroll
                for (int nt = 0; nt < 8; nt++) {
                    mma_bf16(acc[mt][nt], ah[mt], bh[nt]);
                    mma_bf16(acc[mt][nt], ah[mt], bl[nt]);
                    mma_bf16(acc[mt][nt], al[mt], bh[nt]);
                }
        }
        __syncthreads();
    }

    // ---- epilogue: restage via smem (pitch 132), then coalesced stores ----
    float* stg = (float*)smw;
    #pragma unroll
    for (int mt = 0; mt < 2; mt++) {
        #pragma unroll
        for (int nt = 0; nt < 8; nt++) {
            int r0 = wm * 32 + mt * 16 + g;
            int cc = wn * 64 + nt * 8 + 2 * c;
            stg[r0 * 132 + cc]           = acc[mt][nt][0];
            stg[r0 * 132 + cc + 1]       = acc[mt][nt][1];
            stg[(r0 + 8) * 132 + cc]     = acc[mt][nt][2];
            stg[(r0 + 8) * 132 + cc + 1] = acc[mt][nt][3];
        }
    }
    __syncthreads();

    if (PAIR_OUT) {
        const int Nw = N >> 1;
        #pragma unroll 4
        for (int l = 0; l < 32; l++) {
            int id  = t + 256 * l;          // 0..8191
            int row = id >> 6, cw = id & 63;
            float v0 = stg[row * 132 + 2 * cw];
            float v1 = stg[row * 132 + 2 * cw + 1];
            if (bias) { v0 += bias[bn + 2 * cw]; v1 += bias[bn + 2 * cw + 1]; }
            if (GELU) { v0 = gelu_exact(v0); v1 = gelu_exact(v1); }
            uint32_t hi, lo;
            split2(v0, v1, hi, lo);
            size_t o = (size_t)(bm + row) * Nw + (bn >> 1) + cw;
            Ch[o] = hi;
            Cl[o] = lo;
        }
    } else {
        #pragma unroll 4
        for (int l = 0; l < 64; l++) {
            int id  = t + 256 * l;          // 0..16383
            int row = id >> 7, col = id & 127;
            float v = stg[row * 132 + col];
            if (bias) v += bias[bn + col];
            if (GELU) v = gelu_exact(v);
            if (RES)  v += res[(size_t)(bm + row) * N + bn + col];
            C[(size_t)(bm + row) * N + bn + col] = v;
        }
    }
}

// ---------------- block reduce helper ----------------
__device__ __forceinline__ float block_sum(float val, float* red) {
    __syncthreads();
    #pragma unroll
    for (int o = 16; o > 0; o >>= 1) val += __shfl_xor_sync(0xffffffffu, val, o);
    int w = threadIdx.x >> 5;
    if ((threadIdx.x & 31) == 0) red[w] = val;
    __syncthreads();
    if (w == 0) {
        float v = (threadIdx.x < 8) ? red[threadIdx.x] : 0.0f;
        #pragma unroll
        for (int o = 4; o > 0; o >>= 1) v += __shfl_xor_sync(0xffffffffu, v, o);
        if (threadIdx.x == 0) red[0] = v;
    }
    __syncthreads();
    return red[0];
}

// ---------------- LayerNorm -> split bf16 pairs ----------------
__global__ void __launch_bounds__(256) ln_split_kernel(
    const float* __restrict__ x, const float* __restrict__ gam,
    const float* __restrict__ bet, uint32_t* __restrict__ yh,
    uint32_t* __restrict__ yl)
{
    __shared__ float red[8];
    const int row = blockIdx.x;
    const float* xr = x + (size_t)row * HIDN;
    const int t = threadIdx.x;
    float4 xv = *(const float4*)(xr + t * 4);
    float s = xv.x + xv.y + xv.z + xv.w;
    float mu = block_sum(s, red) * (1.0f / HIDN);
    float dx = xv.x - mu, dy = xv.y - mu, dz = xv.z - mu, dw = xv.w - mu;
    float sq = dx * dx + dy * dy + dz * dz + dw * dw;
    float var = block_sum(sq, red) * (1.0f / HIDN);
    float inv = rsqrtf(var + 1e-8f);
    float4 gv = *(const float4*)(gam + t * 4);
    float4 bv = *(const float4*)(bet + t * 4);
    float o0 = dx * inv * gv.x + bv.x;
    float o1 = dy * inv * gv.y + bv.y;
    float o2 = dz * inv * gv.z + bv.z;
    float o3 = dw * inv * gv.w + bv.w;
    uint2 hw, lw;
    split2(o0, o1, hw.x, lw.x);
    split2(o2, o3, hw.y, lw.y);
    ((uint2*)(yh + (size_t)row * (HIDN / 2)))[t] = hw;
    ((uint2*)(yl + (size_t)row * (HIDN / 2)))[t] = lw;
}

// ---------------- positional bias precompute ----------------
__global__ void __launch_bounds__(256) posbias_kernel(
    const float* __restrict__ src, const float* __restrict__ pos,
    float* __restrict__ dst)
{
    const int h  = blockIdx.y;
    const int r0 = blockIdx.x * 16;
    __shared__ float qs[16][HD];
    for (int idx = threadIdx.x; idx < 16 * HD; idx += 256) {
        int r = idx >> 6, d = idx & 63;
        qs[r][d] = src[(size_t)(r0 + r) * HIDN + h * HD + d];
    }
    __syncthreads();
    for (int p = threadIdx.x; p < NP; p += 256) {
        float accv[16];
        #pragma unroll
        for (int r = 0; r < 16; r++) accv[r] = 0.0f;
        for (int d = 0; d < HD; d++) {
            float pv = pos[((size_t)h * HD + d) * NP + p];
            #pragma unroll
            for (int r = 0; r < 16; r++) accv[r] = fmaf(qs[r][d], pv, accv[r]);
        }
        #pragma unroll
        for (int r = 0; r < 16; r++)
            dst[((size_t)h * LQ + (r0 + r)) * NP + p] = accv[r];
    }
}

// ---------------- banded attention -> ctx split pairs ----------------
#define SSTR 321
#define ATT_SMEM ((64 * 65 * 2 + 64 * SSTR) * 4)

__global__ void __launch_bounds__(256) attn_kernel(
    const float* __restrict__ q, const float* __restrict__ k,
    const float* __restrict__ v, const float* __restrict__ c2p,
    const float* __restrict__ p2c, uint32_t* __restrict__ ctxh,
    uint32_t* __restrict__ ctxl)
{
    extern __shared__ float sm[];
    float* Qs = sm;
    float* Ks = Qs + 64 * 65;
    float* Sp = Ks + 64 * 65;

    const int h  = blockIdx.y;
    const int i0 = blockIdx.x * 64;
    const int t  = threadIdx.x;
    const int tx = t & 15, ty = t >> 4;

    for (int idx = t; idx < 64 * HD; idx += 256) {
        int r = idx >> 6, d = idx & 63;
        Qs[r * 65 + d] = q[(size_t)(i0 + r) * HIDN + h * HD + d];
    }

    for (int c = 0; c < 5; c++) {
        const int j0 = i0 - 128 + c * 64;
        __syncthreads();
        for (int idx = t; idx < 64 * HD; idx += 256) {
            int r = idx >> 6, d = idx & 63;
            int j = j0 + r;
            Ks[r * 65 + d] = (j >= 0 && j < LQ)
                                 ? k[(size_t)j * HIDN + h * HD + d] : 0.0f;
        }
        __syncthreads();
        float sacc[4][4];
        #pragma unroll
        for (int r = 0; r < 4; r++)
            #pragma unroll
            for (int cc = 0; cc < 4; cc++) sacc[r][cc] = 0.0f;
        for (int d = 0; d < HD; d++) {
            float a[4], b[4];
            #pragma unroll
            for (int r = 0; r < 4; r++)  a[r]  = Qs[(ty * 4 + r) * 65 + d];
            #pragma unroll
            for (int cc = 0; cc < 4; cc++) b[cc] = Ks[(tx * 4 + cc) * 65 + d];
            #pragma unroll
            for (int r = 0; r < 4; r++)
                #pragma unroll
                for (int cc = 0; cc < 4; cc++)
                    sacc[r][cc] = fmaf(a[r], b[cc], sacc[r][cc]);
        }
        #pragma unroll
        for (int r = 0; r < 4; r++) {
            #pragma unroll
            for (int cc = 0; cc < 4; cc++) {
                int i = i0 + ty * 4 + r;
                int j = j0 + tx * 4 + cc;
                int rel = j - i;
                float s = -1e30f;
                if (j >= 0 && j < LQ && rel >= -PW && rel <= PW) {
                    s = sacc[r][cc]
                      + c2p[((size_t)h * LQ + i) * NP + (PW + rel)]
                      + p2c[((size_t)h * LQ + j) * NP + (PW - rel)];
                }
                Sp[(ty * 4 + r) * SSTR + c * 64 + tx * 4 + cc] = s;
            }
        }
    }
    __syncthreads();

    {
        int r = t >> 2, g = t & 3;
        float* row = Sp + r * SSTR + g * 80;
        float mx = -1e30f;
        for (int x = 0; x < 80; x++) mx = fmaxf(mx, row[x]);
        mx = fmaxf(mx, __shfl_xor_sync(0xffffffffu, mx, 1));
        mx = fmaxf(mx, __shfl_xor_sync(0xffffffffu, mx, 2));
        float sum = 0.0f;
        for (int x = 0; x < 80; x++) {
            float e = __expf(row[x] - mx);
            row[x] = e;
            sum += e;
        }
        sum += __shfl_xor_sync(0xffffffffu, sum, 1);
        sum += __shfl_xor_sync(0xffffffffu, sum, 2);
        float inv = 1.0f / sum;
        for (int x = 0; x < 80; x++) row[x] *= inv;
    }
    __syncthreads();

    float oacc[4][4];
    #pragma unroll
    for (int r = 0; r < 4; r++)
        #pragma unroll
        for (int cc = 0; cc < 4; cc++) oacc[r][cc] = 0.0f;

    for (int c = 0; c < 5; c++) {
        const int j0 = i0 - 128 + c * 64;
        for (int idx = t; idx < 64 * HD; idx += 256) {
            int r = idx >> 6, d = idx & 63;
            int j = j0 + r;
            Ks[r * 65 + d] = (j >= 0 && j < LQ)
                                 ? v[(size_t)j * HIDN + h * HD + d] : 0.0f;
        }
        __syncthreads();
        for (int kk = 0; kk < 64; kk++) {
            float p[4], vv[4];
            #pragma unroll
            for (int r = 0; r < 4; r++)
                p[r] = Sp[(ty * 4 + r) * SSTR + c * 64 + kk];
            #pragma unroll
            for (int cc = 0; cc < 4; cc++)
                vv[cc] = Ks[kk * 65 + tx * 4 + cc];
            #pragma unroll
            for (int r = 0; r < 4; r++)
                #pragma unroll
                for (int cc = 0; cc < 4; cc++)
                    oacc[r][cc] = fmaf(p[r], vv[cc], oacc[r][cc]);
        }
        __syncthreads();
    }

    #pragma unroll
    for (int r = 0; r < 4; r++) {
        uint32_t h0, l0, h1, l1;
        split2(oacc[r][0], oacc[r][1], h0, l0);
        split2(oacc[r][2], oacc[r][3], h1, l1);
        size_t base = (size_t)(i0 + ty * 4 + r) * (HIDN / 2) + h * 32 + tx * 2;
        ctxh[base]     = h0;
        ctxh[base + 1] = h1;
        ctxl[base]     = l0;
        ctxl[base + 1] = l1;
    }
}

// ---------------- launch ----------------
extern "C" void kernel_launch(void* const* d_in, const int* in_sizes, int n_in,
                              void* d_out, int out_size)
{
    const float* hidden    = (const float*)d_in[0];
    const float* wq        = (const float*)d_in[2];
    const float* wk        = (const float*)d_in[3];
    const float* wv        = (const float*)d_in[4];
    const float* pos_key   = (const float*)d_in[5];
    const float* pos_query = (const float*)d_in[6];
    const float* wo        = (const float*)d_in[7];
    const float* bo        = (const float*)d_in[8];
    const float* ln1_g     = (const float*)d_in[9];
    const float* ln1_b     = (const float*)d_in[10];
    const float* ln2_g     = (const float*)d_in[11];
    const float* ln2_b     = (const float*)d_in[12];
    const float* w1        = (const float*)d_in[13];
    const float* b1        = (const float*)d_in[14];
    const float* w2        = (const float*)d_in[15];
    const float* b2        = (const float*)d_in[16];
    float* out = (float*)d_out;

    float *q, *k, *v, *h, *c2p, *p2c;
    uint32_t *x1h, *x1l, *x2h, *x2l, *ctxh, *ctxl, *ffh, *ffl;
    uint32_t *wqh, *wql, *wkh, *wkl, *wvh, *wvl, *woh, *wol;
    uint32_t *w1h, *w1l, *w2h, *w2l;
    cudaGetSymbolAddress((void**)&q,    g_q);
    cudaGetSymbolAddress((void**)&k,    g_k);
    cudaGetSymbolAddress((void**)&v,    g_v);
    cudaGetSymbolAddress((void**)&h,    g_h);
    cudaGetSymbolAddress((void**)&c2p,  g_c2p);
    cudaGetSymbolAddress((void**)&p2c,  g_p2c);
    cudaGetSymbolAddress((void**)&x1h,  g_x1h);
    cudaGetSymbolAddress((void**)&x1l,  g_x1l);
    cudaGetSymbolAddress((void**)&x2h,  g_x2h);
    cudaGetSymbolAddress((void**)&x2l,  g_x2l);
    cudaGetSymbolAddress((void**)&ctxh, g_ctxh);
    cudaGetSymbolAddress((void**)&ctxl, g_ctxl);
    cudaGetSymbolAddress((void**)&ffh,  g_ffh);
    cudaGetSymbolAddress((void**)&ffl,  g_ffl);
    cudaGetSymbolAddress((void**)&wqh,  g_wqh);
    cudaGetSymbolAddress((void**)&wql,  g_wql);
    cudaGetSymbolAddress((void**)&wkh,  g_wkh);
    cudaGetSymbolAddress((void**)&wkl,  g_wkl);
    cudaGetSymbolAddress((void**)&wvh,  g_wvh);
    cudaGetSymbolAddress((void**)&wvl,  g_wvl);
    cudaGetSymbolAddress((void**)&woh,  g_woh);
    cudaGetSymbolAddress((void**)&wol,  g_wol);
    cudaGetSymbolAddress((void**)&w1h,  g_w1h);
    cudaGetSymbolAddress((void**)&w1l,  g_w1l);
    cudaGetSymbolAddress((void**)&w2h,  g_w2h);
    cudaGetSymbolAddress((void**)&w2l,  g_w2l);

    cudaFuncSetAttribute(attn_kernel,
                         cudaFuncAttributeMaxDynamicSharedMemorySize, ATT_SMEM);
    cudaFuncSetAttribute(tgemm_kernel<false, false, false>,
                         cudaFuncAttributeMaxDynamicSharedMemorySize, TG_SMEM);
    cudaFuncSetAttribute(tgemm_kernel<false, true, false>,
                         cudaFuncAttributeMaxDynamicSharedMemorySize, TG_SMEM);
    cudaFuncSetAttribute(tgemm_kernel<true, false, true>,
                         cudaFuncAttributeMaxDynamicSharedMemorySize, TG_SMEM);

    // 0) transpose + split weights -> [N][K/2] bf16 pairs
    transpose_split_kernel<<<dim3(HIDN / 32, HIDN / 32), 256>>>(wq, wqh, wql, HIDN, HIDN);
    transpose_split_kernel<<<dim3(HIDN / 32, HIDN / 32), 256>>>(wk, wkh, wkl, HIDN, HIDN);
    transpose_split_kernel<<<dim3(HIDN / 32, HIDN / 32), 256>>>(wv, wvh, wvl, HIDN, HIDN);
    transpose_split_kernel<<<dim3(HIDN / 32, HIDN / 32), 256>>>(wo, woh, wol, HIDN, HIDN);
    transpose_split_kernel<<<dim3(FFD / 32,  HIDN / 32), 256>>>(w1, w1h, w1l, HIDN, FFD);
    transpose_split_kernel<<<dim3(HIDN / 32, FFD / 32),  256>>>(w2, w2h, w2l, FFD, HIDN);

    // 1) LN1 -> x1 split
    ln_split_kernel<<<LQ, 256>>>(hidden, ln1_g, ln1_b, x1h, x1l);

    // 2) QKV projections (bf16x3)
    dim3 gP(HIDN / 128, LQ / 128);
    tgemm_kernel<false, false, false><<<gP, 256, TG_SMEM>>>(
        LQ, HIDN, HIDN, x1h, x1l, wqh, wql, q, nullptr, nullptr, nullptr, nullptr);
    tgemm_kernel<false, false, false><<<gP, 256, TG_SMEM>>>(
        LQ, HIDN, HIDN, x1h, x1l, wkh, wkl, k, nullptr, nullptr, nullptr, nullptr);
    tgemm_kernel<false, false, false><<<gP, 256, TG_SMEM>>>(
        LQ, HIDN, HIDN, x1h, x1l, wvh, wvl, v, nullptr, nullptr, nullptr, nullptr);

    // 3) positional bias tables
    dim3 gB(LQ / 16, NH);
    posbias_kernel<<<gB, 256>>>(q, pos_key,   c2p);
    posbias_kernel<<<gB, 256>>>(k, pos_query, p2c);

    // 4) banded attention -> ctx split
    attn_kernel<<<dim3(LQ / 64, NH), 256, ATT_SMEM>>>(q, k, v, c2p, p2c, ctxh, ctxl);

    // 5) output projection + bias + residual -> h (f32)
    tgemm_kernel<false, true, false><<<gP, 256, TG_SMEM>>>(
        LQ, HIDN, HIDN, ctxh, ctxl, woh, wol, h, nullptr, nullptr, bo, hidden);

    // 6) LN2 -> x2 split
    ln_split_kernel<<<LQ, 256>>>(h, ln2_g, ln2_b, x2h, x2l);

    // 7) FFN up + GELU -> ff split
    dim3 gF(FFD / 128, LQ / 128);
    tgemm_kernel<true, false, true><<<gF, 256, TG_SMEM>>>(
        LQ, FFD, HIDN, x2h, x2l, w1h, w1l, nullptr, ffh, ffl, b1, nullptr);

    // 8) FFN down + bias + residual -> out (f32)
    tgemm_kernel<false, true, false><<<gP, 256, TG_SMEM>>>(
        LQ, HIDN, FFD, ffh, ffl, w2h, w2l, out, nullptr, nullptr, b2, h);
}

// round 8
// speedup vs baseline: 1.0123x; 1.0123x over previous
#include <cuda_runtime.h>
#include <cuda_bf16.h>
#include <math.h>
#include <cstdint>

// ---------------- problem constants ----------------
#define LQ   2048
#define HIDN 1024
#define NH   16
#define HD   64
#define FFD  4096
#define PW   128
#define NP   257

// ---------------- scratch ----------------
__device__ float g_q  [LQ * HIDN];
__device__ float g_k  [LQ * HIDN];
__device__ float g_v  [LQ * HIDN];
__device__ float g_h  [LQ * HIDN];
__device__ float g_c2p[NH * LQ * NP];
__device__ float g_p2c[NH * LQ * NP];
// bf16 split pairs, packed 2 elems per uint32 (even elem in low 16 bits)
__device__ uint32_t g_x1h [LQ * HIDN / 2];
__device__ uint32_t g_x1l [LQ * HIDN / 2];
__device__ uint32_t g_x2h [LQ * HIDN / 2];
__device__ uint32_t g_x2l [LQ * HIDN / 2];
__device__ uint32_t g_ctxh[LQ * HIDN / 2];
__device__ uint32_t g_ctxl[LQ * HIDN / 2];
__device__ uint32_t g_ffh [LQ * FFD  / 2];
__device__ uint32_t g_ffl [LQ * FFD  / 2];
// transposed split weights: [N][K/2] words
__device__ uint32_t g_wqh[HIDN * HIDN / 2];
__device__ uint32_t g_wql[HIDN * HIDN / 2];
__device__ uint32_t g_wkh[HIDN * HIDN / 2];
__device__ uint32_t g_wkl[HIDN * HIDN / 2];
__device__ uint32_t g_wvh[HIDN * HIDN / 2];
__device__ uint32_t g_wvl[HIDN * HIDN / 2];
__device__ uint32_t g_woh[HIDN * HIDN / 2];
__device__ uint32_t g_wol[HIDN * HIDN / 2];
__device__ uint32_t g_w1h[FFD * HIDN / 2];
__device__ uint32_t g_w1l[FFD * HIDN / 2];
__device__ uint32_t g_w2h[HIDN * FFD / 2];
__device__ uint32_t g_w2l[HIDN * FFD / 2];

// ---------------- helpers ----------------
__device__ __forceinline__ uint32_t smem_u32(const void* p) {
    uint32_t a;
    asm("{ .reg .u64 t; cvta.to.shared.u64 t, %1; cvt.u32.u64 %0, t; }"
        : "=r"(a) : "l"(p));
    return a;
}

#define CP_ASYNC16(dst, src) \
    asm volatile("cp.async.cg.shared.global [%0], [%1], 16;" \
                 :: "r"(dst), "l"(src) : "memory")
#define CP_ASYNC_COMMIT() asm volatile("cp.async.commit_group;" ::: "memory")
#define CP_ASYNC_WAIT0()  asm volatile("cp.async.wait_group 0;" ::: "memory")

#define LDSM_X4(r0, r1, r2, r3, addr) \
    asm volatile("ldmatrix.sync.aligned.m8n8.x4.shared.b16 {%0,%1,%2,%3}, [%4];" \
                 : "=r"(r0), "=r"(r1), "=r"(r2), "=r"(r3) : "r"(addr))

// split x0,x1 into packed bf16 hi pair and lo pair (x0 -> low 16 bits)
__device__ __forceinline__ void split2(float x0, float x1,
                                       uint32_t& hi, uint32_t& lo)
{
    asm("cvt.rn.bf16x2.f32 %0, %1, %2;" : "=r"(hi) : "f"(x1), "f"(x0));
    float f0 = __uint_as_float(hi << 16);
    float f1 = __uint_as_float(hi & 0xffff0000u);
    float l0 = x0 - f0, l1 = x1 - f1;
    asm("cvt.rn.bf16x2.f32 %0, %1, %2;" : "=r"(lo) : "f"(l1), "f"(l0));
}

// bf16 m16n8k16 mma (baseline PTX sm_80+)
__device__ __forceinline__ void mma_bf16(float* d, const uint32_t* a,
                                         const uint32_t* b)
{
    asm volatile(
        "mma.sync.aligned.m16n8k16.row.col.f32.bf16.bf16.f32 "
        "{%0,%1,%2,%3}, {%4,%5,%6,%7}, {%8,%9}, {%0,%1,%2,%3};"
        : "+f"(d[0]), "+f"(d[1]), "+f"(d[2]), "+f"(d[3])
        : "r"(a[0]), "r"(a[1]), "r"(a[2]), "r"(a[3]),
          "r"(b[0]), "r"(b[1]));
}

__device__ __forceinline__ float gelu_exact(float x) {
    return 0.5f * x * (1.0f + erff(x * 0.70710678118654752440f));
}

// ---------------- transpose + split: src[R,C] f32 -> dh/dl [C][R/2] words ----
__global__ void __launch_bounds__(256) transpose_split_kernel(
    const float* __restrict__ src, uint32_t* __restrict__ dh,
    uint32_t* __restrict__ dl, int R, int C)
{
    __shared__ float tl[32][33];
    int c0 = blockIdx.x * 32, r0 = blockIdx.y * 32;
    int x = threadIdx.x & 31, y = threadIdx.x >> 5;
    #pragma unroll
    for (int i = 0; i < 32; i += 8)
        tl[y + i][x] = src[(size_t)(r0 + y + i) * C + c0 + x];
    __syncthreads();
    int xx = threadIdx.x & 15;
    int yy = threadIdx.x >> 4;
    int Rw = R >> 1;
    #pragma unroll
    for (int i = 0; i < 2; i++) {
        int n = c0 + yy + i * 16;
        uint32_t hi, lo;
        split2(tl[2 * xx][yy + i * 16], tl[2 * xx + 1][yy + i * 16], hi, lo);
        dh[(size_t)n * Rw + (r0 >> 1) + xx] = hi;
        dl[(size_t)n * Rw + (r0 >> 1) + xx] = lo;
    }
}

// ---------------- bf16x3 GEMM with ldmatrix frag loads ----------------
// C[M,N] = A[M,K] @ Bt[N,K]^T via ah*bh + ah*bl + al*bh.
// Tile 128x128, K-chunk 32 (16 words), 8 warps (4x2), cp.async dbl-buffer.
#define WPITCH 20
#define ARRW (128 * WPITCH)          // words per array
#define BUFW (4 * ARRW)              // Ahi Alo Bhi Blo
#define TG_SMEM 81920

template <bool GELU, bool RES, bool PAIR_OUT>
__global__ void __launch_bounds__(256) tgemm_kernel(
    int M, int N, int K,
    const uint32_t* __restrict__ Ah, const uint32_t* __restrict__ Al,
    const uint32_t* __restrict__ Bh, const uint32_t* __restrict__ Bl,
    float* __restrict__ C, uint32_t* __restrict__ Ch,
    uint32_t* __restrict__ Cl,
    const float* __restrict__ bias, const float* __restrict__ res)
{
    extern __shared__ uint32_t smw[];
    uint32_t sb = smem_u32(smw);
    const int t    = threadIdx.x;
    const int wid  = t >> 5;
    const int lane = t & 31;
    const int g    = lane >> 2;
    const int c    = lane & 3;
    const int wm   = wid & 3;
    const int wn   = wid >> 2;
    const int bm   = blockIdx.y * 128;
    const int bn   = blockIdx.x * 128;
    const int Kw   = K >> 1;
    const int nk   = K >> 5;

    // per-lane ldmatrix base offsets (bytes)
    // A x4: lanes 0-7 rows 0-7 k0; 8-15 rows 8-15 k0; 16-23 rows 0-7 k+4w; 24-31 rows 8-15 k+4w
    const uint32_t a_loff =
        ((uint32_t)((wm * 32 + (lane & 15)) * WPITCH + (lane >> 4) * 4)) * 4u;
    // B x4: lanes 0-7 tile rows 0-7 k0; 8-15 same rows k+4w; 16-23 rows 8-15 k0; 24-31 rows 8-15 k+4w
    const uint32_t b_loff =
        ((uint32_t)((wn * 64 + (lane & 7) + ((lane >> 4) & 1) * 8) * WPITCH +
                    ((lane >> 3) & 1) * 4)) * 4u;

    float acc[2][8][4];
    #pragma unroll
    for (int mt = 0; mt < 2; mt++)
        #pragma unroll
        for (int nt = 0; nt < 8; nt++)
            #pragma unroll
            for (int r = 0; r < 4; r++) acc[mt][nt][r] = 0.0f;

    auto load_chunk = [&](int ck, int buf) {
        uint32_t db = sb + buf * (BUFW * 4u);
        #pragma unroll
        for (int half = 0; half < 2; half++) {
            int id = t + 256 * half;
            int r  = id >> 2;
            int f  = (id & 3) * 4;
            uint32_t doff = (uint32_t)(r * WPITCH + f) * 4u;
            size_t ao = (size_t)(bm + r) * Kw + ck * 16 + f;
            size_t bo = (size_t)(bn + r) * Kw + ck * 16 + f;
            CP_ASYNC16(db + doff,                  Ah + ao);
            CP_ASYNC16(db + ARRW * 4u + doff,      Al + ao);
            CP_ASYNC16(db + 2u * ARRW * 4u + doff, Bh + bo);
            CP_ASYNC16(db + 3u * ARRW * 4u + doff, Bl + bo);
        }
    };

    load_chunk(0, 0);
    CP_ASYNC_COMMIT();

    for (int i = 0; i < nk; i++) {
        CP_ASYNC_WAIT0();
        __syncthreads();
        if (i + 1 < nk) { load_chunk(i + 1, (i + 1) & 1); CP_ASYNC_COMMIT(); }

        uint32_t Ash = sb + (uint32_t)(i & 1) * (BUFW * 4u);
        uint32_t Asl = Ash + ARRW * 4u;
        uint32_t Bsh = Ash + 2u * ARRW * 4u;
        uint32_t Bsl = Ash + 3u * ARRW * 4u;

        #pragma unroll
        for (int s = 0; s < 2; s++) {
            uint32_t ah[2][4], al[2][4];
            #pragma unroll
            for (int mt = 0; mt < 2; mt++) {
                uint32_t ao = a_loff + (uint32_t)(mt * 16 * WPITCH + s * 8) * 4u;
                LDSM_X4(ah[mt][0], ah[mt][1], ah[mt][2], ah[mt][3], Ash + ao);
                LDSM_X4(al[mt][0], al[mt][1], al[mt][2], al[mt][3], Asl + ao);
            }
            #pragma unroll
            for (int ntp = 0; ntp < 4; ntp++) {
                uint32_t bo = b_loff + (uint32_t)(ntp * 16 * WPITCH + s * 8) * 4u;
                uint32_t bh[2][2], bl[2][2];
                LDSM_X4(bh[0][0], bh[0][1], bh[1][0], bh[1][1], Bsh + bo);
                LDSM_X4(bl[0][0], bl[0][1], bl[1][0], bl[1][1], Bsl + bo);
                #pragma unroll
                for (int q = 0; q < 2; q++) {
                    int nt = ntp * 2 + q;
                    #pragma unroll
                    for (int mt = 0; mt < 2; mt++) {
                        mma_bf16(acc[mt][nt], ah[mt], bh[q]);
                        mma_bf16(acc[mt][nt], ah[mt], bl[q]);
                        mma_bf16(acc[mt][nt], al[mt], bh[q]);
                    }
                }
            }
        }
        __syncthreads();
    }

    // ---- epilogue: restage via smem (pitch 132), then coalesced stores ----
    float* stg = (float*)smw;
    #pragma unroll
    for (int mt = 0; mt < 2; mt++) {
        #pragma unroll
        for (int nt = 0; nt < 8; nt++) {
            int r0 = wm * 32 + mt * 16 + g;
            int cc = wn * 64 + nt * 8 + 2 * c;
            stg[r0 * 132 + cc]           = acc[mt][nt][0];
            stg[r0 * 132 + cc + 1]       = acc[mt][nt][1];
            stg[(r0 + 8) * 132 + cc]     = acc[mt][nt][2];
            stg[(r0 + 8) * 132 + cc + 1] = acc[mt][nt][3];
        }
    }
    __syncthreads();

    if (PAIR_OUT) {
        const int Nw = N >> 1;
        #pragma unroll 4
        for (int l = 0; l < 32; l++) {
            int id  = t + 256 * l;
            int row = id >> 6, cw = id & 63;
            float v0 = stg[row * 132 + 2 * cw];
            float v1 = stg[row * 132 + 2 * cw + 1];
            if (bias) { v0 += bias[bn + 2 * cw]; v1 += bias[bn + 2 * cw + 1]; }
            if (GELU) { v0 = gelu_exact(v0); v1 = gelu_exact(v1); }
            uint32_t hi, lo;
            split2(v0, v1, hi, lo);
            size_t o = (size_t)(bm + row) * Nw + (bn >> 1) + cw;
            Ch[o] = hi;
            Cl[o] = lo;
        }
    } else {
        #pragma unroll 4
        for (int l = 0; l < 64; l++) {
            int id  = t + 256 * l;
            int row = id >> 7, col = id & 127;
            float v = stg[row * 132 + col];
            if (bias) v += bias[bn + col];
            if (GELU) v = gelu_exact(v);
            if (RES)  v += res[(size_t)(bm + row) * N + bn + col];
            C[(size_t)(bm + row) * N + bn + col] = v;
        }
    }
}

// ---------------- block reduce helper ----------------
__device__ __forceinline__ float block_sum(float val, float* red) {
    __syncthreads();
    #pragma unroll
    for (int o = 16; o > 0; o >>= 1) val += __shfl_xor_sync(0xffffffffu, val, o);
    int w = threadIdx.x >> 5;
    if ((threadIdx.x & 31) == 0) red[w] = val;
    __syncthreads();
    if (w == 0) {
        float v = (threadIdx.x < 8) ? red[threadIdx.x] : 0.0f;
        #pragma unroll
        for (int o = 4; o > 0; o >>= 1) v += __shfl_xor_sync(0xffffffffu, v, o);
        if (threadIdx.x == 0) red[0] = v;
    }
    __syncthreads();
    return red[0];
}

// ---------------- LayerNorm -> split bf16 pairs ----------------
__global__ void __launch_bounds__(256) ln_split_kernel(
    const float* __restrict__ x, const float* __restrict__ gam,
    const float* __restrict__ bet, uint32_t* __restrict__ yh,
    uint32_t* __restrict__ yl)
{
    __shared__ float red[8];
    const int row = blockIdx.x;
    const float* xr = x + (size_t)row * HIDN;
    const int t = threadIdx.x;
    float4 xv = *(const float4*)(xr + t * 4);
    float s = xv.x + xv.y + xv.z + xv.w;
    float mu = block_sum(s, red) * (1.0f / HIDN);
    float dx = xv.x - mu, dy = xv.y - mu, dz = xv.z - mu, dw = xv.w - mu;
    float sq = dx * dx + dy * dy + dz * dz + dw * dw;
    float var = block_sum(sq, red) * (1.0f / HIDN);
    float inv = rsqrtf(var + 1e-8f);
    float4 gv = *(const float4*)(gam + t * 4);
    float4 bv = *(const float4*)(bet + t * 4);
    float o0 = dx * inv * gv.x + bv.x;
    float o1 = dy * inv * gv.y + bv.y;
    float o2 = dz * inv * gv.z + bv.z;
    float o3 = dw * inv * gv.w + bv.w;
    uint2 hw, lw;
    split2(o0, o1, hw.x, lw.x);
    split2(o2, o3, hw.y, lw.y);
    ((uint2*)(yh + (size_t)row * (HIDN / 2)))[t] = hw;
    ((uint2*)(yl + (size_t)row * (HIDN / 2)))[t] = lw;
}

// ---------------- positional bias precompute ----------------
__global__ void __launch_bounds__(256) posbias_kernel(
    const float* __restrict__ src, const float* __restrict__ pos,
    float* __restrict__ dst)
{
    const int h  = blockIdx.y;
    const int r0 = blockIdx.x * 16;
    __shared__ float qs[16][HD];
    for (int idx = threadIdx.x; idx < 16 * HD; idx += 256) {
        int r = idx >> 6, d = idx & 63;
        qs[r][d] = src[(size_t)(r0 + r) * HIDN + h * HD + d];
    }
    __syncthreads();
    for (int p = threadIdx.x; p < NP; p += 256) {
        float accv[16];
        #pragma unroll
        for (int r = 0; r < 16; r++) accv[r] = 0.0f;
        for (int d = 0; d < HD; d++) {
            float pv = pos[((size_t)h * HD + d) * NP + p];
            #pragma unroll
            for (int r = 0; r < 16; r++) accv[r] = fmaf(qs[r][d], pv, accv[r]);
        }
        #pragma unroll
        for (int r = 0; r < 16; r++)
            dst[((size_t)h * LQ + (r0 + r)) * NP + p] = accv[r];
    }
}

// ---------------- banded attention -> ctx split pairs ----------------
#define SSTR 321
#define ATT_SMEM ((64 * 65 * 2 + 64 * SSTR) * 4)

__global__ void __launch_bounds__(256) attn_kernel(
    const float* __restrict__ q, const float* __restrict__ k,
    const float* __restrict__ v, const float* __restrict__ c2p,
    const float* __restrict__ p2c, uint32_t* __restrict__ ctxh,
    uint32_t* __restrict__ ctxl)
{
    extern __shared__ float sm[];
    float* Qs = sm;
    float* Ks = Qs + 64 * 65;
    float* Sp = Ks + 64 * 65;

    const int h  = blockIdx.y;
    const int i0 = blockIdx.x * 64;
    const int t  = threadIdx.x;
    const int tx = t & 15, ty = t >> 4;

    for (int idx = t; idx < 64 * HD; idx += 256) {
        int r = idx >> 6, d = idx & 63;
        Qs[r * 65 + d] = q[(size_t)(i0 + r) * HIDN + h * HD + d];
    }

    for (int c = 0; c < 5; c++) {
        const int j0 = i0 - 128 + c * 64;
        __syncthreads();
        for (int idx = t; idx < 64 * HD; idx += 256) {
            int r = idx >> 6, d = idx & 63;
            int j = j0 + r;
            Ks[r * 65 + d] = (j >= 0 && j < LQ)
                                 ? k[(size_t)j * HIDN + h * HD + d] : 0.0f;
        }
        __syncthreads();
        float sacc[4][4];
        #pragma unroll
        for (int r = 0; r < 4; r++)
            #pragma unroll
            for (int cc = 0; cc < 4; cc++) sacc[r][cc] = 0.0f;
        for (int d = 0; d < HD; d++) {
            float a[4], b[4];
            #pragma unroll
            for (int r = 0; r < 4; r++)  a[r]  = Qs[(ty * 4 + r) * 65 + d];
            #pragma unroll
            for (int cc = 0; cc < 4; cc++) b[cc] = Ks[(tx * 4 + cc) * 65 + d];
            #pragma unroll
            for (int r = 0; r < 4; r++)
                #pragma unroll
                for (int cc = 0; cc < 4; cc++)
                    sacc[r][cc] = fmaf(a[r], b[cc], sacc[r][cc]);
        }
        #pragma unroll
        for (int r = 0; r < 4; r++) {
            #pragma unroll
            for (int cc = 0; cc < 4; cc++) {
                int i = i0 + ty * 4 + r;
                int j = j0 + tx * 4 + cc;
                int rel = j - i;
                float s = -1e30f;
                if (j >= 0 && j < LQ && rel >= -PW && rel <= PW) {
                    s = sacc[r][cc]
                      + c2p[((size_t)h * LQ + i) * NP + (PW + rel)]
                      + p2c[((size_t)h * LQ + j) * NP + (PW - rel)];
                }
                Sp[(ty * 4 + r) * SSTR + c * 64 + tx * 4 + cc] = s;
            }
        }
    }
    __syncthreads();

    {
        int r = t >> 2, g = t & 3;
        float* row = Sp + r * SSTR + g * 80;
        float mx = -1e30f;
        for (int x = 0; x < 80; x++) mx = fmaxf(mx, row[x]);
        mx = fmaxf(mx, __shfl_xor_sync(0xffffffffu, mx, 1));
        mx = fmaxf(mx, __shfl_xor_sync(0xffffffffu, mx, 2));
        float sum = 0.0f;
        for (int x = 0; x < 80; x++) {
            float e = __expf(row[x] - mx);
            row[x] = e;
            sum += e;
        }
        sum += __shfl_xor_sync(0xffffffffu, sum, 1);
        sum += __shfl_xor_sync(0xffffffffu, sum, 2);
        float inv = 1.0f / sum;
        for (int x = 0; x < 80; x++) row[x] *= inv;
    }
    __syncthreads();

    float oacc[4][4];
    #pragma unroll
    for (int r = 0; r < 4; r++)
        #pragma unroll
        for (int cc = 0; cc < 4; cc++) oacc[r][cc] = 0.0f;

    for (int c = 0; c < 5; c++) {
        const int j0 = i0 - 128 + c * 64;
        for (int idx = t; idx < 64 * HD; idx += 256) {
            int r = idx >> 6, d = idx & 63;
            int j = j0 + r;
            Ks[r * 65 + d] = (j >= 0 && j < LQ)
                                 ? v[(size_t)j * HIDN + h * HD + d] : 0.0f;
        }
        __syncthreads();
        for (int kk = 0; kk < 64; kk++) {
            float p[4], vv[4];
            #pragma unroll
            for (int r = 0; r < 4; r++)
                p[r] = Sp[(ty * 4 + r) * SSTR + c * 64 + kk];
            #pragma unroll
            for (int cc = 0; cc < 4; cc++)
                vv[cc] = Ks[kk * 65 + tx * 4 + cc];
            #pragma unroll
            for (int r = 0; r < 4; r++)
                #pragma unroll
                for (int cc = 0; cc < 4; cc++)
                    oacc[r][cc] = fmaf(p[r], vv[cc], oacc[r][cc]);
        }
        __syncthreads();
    }

    #pragma unroll
    for (int r = 0; r < 4; r++) {
        uint32_t h0, l0, h1, l1;
        split2(oacc[r][0], oacc[r][1], h0, l0);
        split2(oacc[r][2], oacc[r][3], h1, l1);
        size_t base = (size_t)(i0 + ty * 4 + r) * (HIDN / 2) + h * 32 + tx * 2;
        ctxh[base]     = h0;
        ctxh[base + 1] = h1;
        ctxl[base]     = l0;
        ctxl[base + 1] = l1;
    }
}

// ---------------- launch ----------------
extern "C" void kernel_launch(void* const* d_in, const int* in_sizes, int n_in,
                              void* d_out, int out_size)
{
    const float* hidden    = (const float*)d_in[0];
    const float* wq        = (const float*)d_in[2];
    const float* wk        = (const float*)d_in[3];
    const float* wv        = (const float*)d_in[4];
    const float* pos_key   = (const float*)d_in[5];
    const float* pos_query = (const float*)d_in[6];
    const float* wo        = (const float*)d_in[7];
    const float* bo        = (const float*)d_in[8];
    const float* ln1_g     = (const float*)d_in[9];
    const float* ln1_b     = (const float*)d_in[10];
    const float* ln2_g     = (const float*)d_in[11];
    const float* ln2_b     = (const float*)d_in[12];
    const float* w1        = (const float*)d_in[13];
    const float* b1        = (const float*)d_in[14];
    const float* w2        = (const float*)d_in[15];
    const float* b2        = (const float*)d_in[16];
    float* out = (float*)d_out;

    float *q, *k, *v, *h, *c2p, *p2c;
    uint32_t *x1h, *x1l, *x2h, *x2l, *ctxh, *ctxl, *ffh, *ffl;
    uint32_t *wqh, *wql, *wkh, *wkl, *wvh, *wvl, *woh, *wol;
    uint32_t *w1h, *w1l, *w2h, *w2l;
    cudaGetSymbolAddress((void**)&q,    g_q);
    cudaGetSymbolAddress((void**)&k,    g_k);
    cudaGetSymbolAddress((void**)&v,    g_v);
    cudaGetSymbolAddress((void**)&h,    g_h);
    cudaGetSymbolAddress((void**)&c2p,  g_c2p);
    cudaGetSymbolAddress((void**)&p2c,  g_p2c);
    cudaGetSymbolAddress((void**)&x1h,  g_x1h);
    cudaGetSymbolAddress((void**)&x1l,  g_x1l);
    cudaGetSymbolAddress((void**)&x2h,  g_x2h);
    cudaGetSymbolAddress((void**)&x2l,  g_x2l);
    cudaGetSymbolAddress((void**)&ctxh, g_ctxh);
    cudaGetSymbolAddress((void**)&ctxl, g_ctxl);
    cudaGetSymbolAddress((void**)&ffh,  g_ffh);
    cudaGetSymbolAddress((void**)&ffl,  g_ffl);
    cudaGetSymbolAddress((void**)&wqh,  g_wqh);
    cudaGetSymbolAddress((void**)&wql,  g_wql);
    cudaGetSymbolAddress((void**)&wkh,  g_wkh);
    cudaGetSymbolAddress((void**)&wkl,  g_wkl);
    cudaGetSymbolAddress((void**)&wvh,  g_wvh);
    cudaGetSymbolAddress((void**)&wvl,  g_wvl);
    cudaGetSymbolAddress((void**)&woh,  g_woh);
    cudaGetSymbolAddress((void**)&wol,  g_wol);
    cudaGetSymbolAddress((void**)&w1h,  g_w1h);
    cudaGetSymbolAddress((void**)&w1l,  g_w1l);
    cudaGetSymbolAddress((void**)&w2h,  g_w2h);
    cudaGetSymbolAddress((void**)&w2l,  g_w2l);

    cudaFuncSetAttribute(attn_kernel,
                         cudaFuncAttributeMaxDynamicSharedMemorySize, ATT_SMEM);
    cudaFuncSetAttribute(tgemm_kernel<false, false, false>,
                         cudaFuncAttributeMaxDynamicSharedMemorySize, TG_SMEM);
    cudaFuncSetAttribute(tgemm_kernel<false, true, false>,
                         cudaFuncAttributeMaxDynamicSharedMemorySize, TG_SMEM);
    cudaFuncSetAttribute(tgemm_kernel<true, false, true>,
                         cudaFuncAttributeMaxDynamicSharedMemorySize, TG_SMEM);

    // 0) transpose + split weights -> [N][K/2] bf16 pairs
    transpose_split_kernel<<<dim3(HIDN / 32, HIDN / 32), 256>>>(wq, wqh, wql, HIDN, HIDN);
    transpose_split_kernel<<<dim3(HIDN / 32, HIDN / 32), 256>>>(wk, wkh, wkl, HIDN, HIDN);
    transpose_split_kernel<<<dim3(HIDN / 32, HIDN / 32), 256>>>(wv, wvh, wvl, HIDN, HIDN);
    transpose_split_kernel<<<dim3(HIDN / 32, HIDN / 32), 256>>>(wo, woh, wol, HIDN, HIDN);
    transpose_split_kernel<<<dim3(FFD / 32,  HIDN / 32), 256>>>(w1, w1h, w1l, HIDN, FFD);
    transpose_split_kernel<<<dim3(HIDN / 32, FFD / 32),  256>>>(w2, w2h, w2l, FFD, HIDN);

    // 1) LN1 -> x1 split
    ln_split_kernel<<<LQ, 256>>>(hidden, ln1_g, ln1_b, x1h, x1l);

    // 2) QKV projections (bf16x3 + ldmatrix)
    dim3 gP(HIDN / 128, LQ / 128);
    tgemm_kernel<false, false, false><<<gP, 256, TG_SMEM>>>(
        LQ, HIDN, HIDN, x1h, x1l, wqh, wql, q, nullptr, nullptr, nullptr, nullptr);
    tgemm_kernel<false, false, false><<<gP, 256, TG_SMEM>>>(
        LQ, HIDN, HIDN, x1h, x1l, wkh, wkl, k, nullptr, nullptr, nullptr, nullptr);
    tgemm_kernel<false, false, false><<<gP, 256, TG_SMEM>>>(
        LQ, HIDN, HIDN, x1h, x1l, wvh, wvl, v, nullptr, nullptr, nullptr, nullptr);

    // 3) positional bias tables
    dim3 gB(LQ / 16, NH);
    posbias_kernel<<<gB, 256>>>(q, pos_key,   c2p);
    posbias_kernel<<<gB, 256>>>(k, pos_query, p2c);

    // 4) banded attention -> ctx split
    attn_kernel<<<dim3(LQ / 64, NH), 256, ATT_SMEM>>>(q, k, v, c2p, p2c, ctxh, ctxl);

    // 5) output projection + bias + residual -> h (f32)
    tgemm_kernel<false, true, false><<<gP, 256, TG_SMEM>>>(
        LQ, HIDN, HIDN, ctxh, ctxl, woh, wol, h, nullptr, nullptr, bo, hidden);

    // 6) LN2 -> x2 split
    ln_split_kernel<<<LQ, 256>>>(h, ln2_g, ln2_b, x2h, x2l);

    // 7) FFN up + GELU -> ff split
    dim3 gF(FFD / 128, LQ / 128);
    tgemm_kernel<true, false, true><<<gF, 256, TG_SMEM>>>(
        LQ, FFD, HIDN, x2h, x2l, w1h, w1l, nullptr, ffh, ffl, b1, nullptr);

    // 8) FFN down + bias + residual -> out (f32)
    tgemm_kernel<false, true, false><<<gP, 256, TG_SMEM>>>(
        LQ, HIDN, FFD, ffh, ffl, w2h, w2l, out, nullptr, nullptr, b2, h);
}